// round 6
// baseline (speedup 1.0000x reference)
#include <cuda_runtime.h>

#define NN   100000
#define EE   3200000
#define HH   16
#define DIN  128
#define DOUT 12

// ---------------- static device scratch (no allocation allowed) -------------
__device__ float g_deg[NN];
__device__ float g_dis[NN];
__device__ float g_selfw[NN];
__device__ int   g_cnt[NN];     // per-node incoming-edge count (histogram)
__device__ int   g_start[NN];   // CSR start offsets (exclusive scan of g_cnt)
__device__ int   g_cur[NN];     // scatter cursors; equals count after scatter
__device__ int2  g_edge[EE];    // packed (src, __float_as_int(norm)) grouped by dst
__device__ float g_hwA[NN * HH];
__device__ float g_hwB[NN * HH];
__device__ int   g_bsum[128];
__device__ int   g_is64;        // 1 if edge_index is int64 on device, 0 if int32

// ---------------- dtype sniffer for edge_index ------------------------------
// int64 little-endian values < 2^31 have every odd 32-bit word == 0.
// Genuine int32 indices (random in [0, N)) cannot have 2048 consecutive
// odd words all zero.
__global__ void k_detect(const int* __restrict__ ei32) {
    __shared__ int sOr;
    if (threadIdx.x == 0) sOr = 0;
    __syncthreads();
    int v = 0;
    for (int i = threadIdx.x; i < 2048; i += 256) v |= ei32[2 * i + 1];
    atomicOr(&sOr, v);
    __syncthreads();
    if (threadIdx.x == 0) g_is64 = (sOr == 0) ? 1 : 0;
}

__device__ __forceinline__ int load_idx(const int* __restrict__ ei32,
                                        int idx, int is64) {
    // int64 case: value fits in low 32 bits (indices < 2^31)
    return is64 ? ei32[2 * idx] : ei32[idx];
}

// ---------------- setup kernels --------------------------------------------
__global__ void k_init() {
    int i = blockIdx.x * blockDim.x + threadIdx.x;
    if (i < NN) { g_deg[i] = 0.f; g_cnt[i] = 0; g_cur[i] = 0; }
}

__global__ void k_pass1(const int* __restrict__ ei,
                        const float* __restrict__ ew) {
    int e = blockIdx.x * blockDim.x + threadIdx.x;
    if (e < EE) {
        int is64 = g_is64;
        int c = load_idx(ei, EE + e, is64);   // col = destination
        atomicAdd(&g_deg[c], ew[e]);
        atomicAdd(&g_cnt[c], 1);
    }
}

__global__ void k_node() {
    int i = blockIdx.x * blockDim.x + threadIdx.x;
    if (i < NN) {
        float d = g_deg[i] + 1.0f;            // + self loop
        g_dis[i]   = rsqrtf(d);
        g_selfw[i] = 1.0f / d;
    }
}

// exclusive scan of g_cnt -> g_start (98 blocks x 1024 items)
__global__ void k_scan1() {
    __shared__ int sh[256];
    int t = threadIdx.x;
    int base = blockIdx.x * 1024 + t * 4;
    int v0 = (base + 0 < NN) ? g_cnt[base + 0] : 0;
    int v1 = (base + 1 < NN) ? g_cnt[base + 1] : 0;
    int v2 = (base + 2 < NN) ? g_cnt[base + 2] : 0;
    int v3 = (base + 3 < NN) ? g_cnt[base + 3] : 0;
    int loc = v0 + v1 + v2 + v3;
    sh[t] = loc;
    __syncthreads();
    for (int off = 1; off < 256; off <<= 1) {
        int x = (t >= off) ? sh[t - off] : 0;
        __syncthreads();
        sh[t] += x;
        __syncthreads();
    }
    int run = sh[t] - loc;                    // exclusive
    if (base + 0 < NN) { g_start[base + 0] = run; run += v0; }
    if (base + 1 < NN) { g_start[base + 1] = run; run += v1; }
    if (base + 2 < NN) { g_start[base + 2] = run; run += v2; }
    if (base + 3 < NN) { g_start[base + 3] = run; }
    if (t == 255) g_bsum[blockIdx.x] = sh[255];
}

__global__ void k_scan2(int nb) {
    __shared__ int sh[128];
    int t = threadIdx.x;
    int v = (t < nb) ? g_bsum[t] : 0;
    sh[t] = v;
    __syncthreads();
    for (int off = 1; off < 128; off <<= 1) {
        int x = (t >= off) ? sh[t - off] : 0;
        __syncthreads();
        sh[t] += x;
        __syncthreads();
    }
    if (t < nb) g_bsum[t] = sh[t] - v;        // exclusive
}

__global__ void k_scan3() {
    int add = g_bsum[blockIdx.x];
    int base = blockIdx.x * 1024 + threadIdx.x * 4;
    #pragma unroll
    for (int i = 0; i < 4; i++)
        if (base + i < NN) g_start[base + i] += add;
}

__global__ void k_scatter(const int* __restrict__ ei,
                          const float* __restrict__ ew) {
    int e = blockIdx.x * blockDim.x + threadIdx.x;
    if (e < EE) {
        int is64 = g_is64;
        int r = load_idx(ei, e, is64);
        int c = load_idx(ei, EE + e, is64);
        float nrm = g_dis[r] * ew[e] * g_dis[c];
        int p = g_start[c] + atomicAdd(&g_cur[c], 1);
        g_edge[p] = make_int2(r, __float_as_int(nrm));
    }
}

// ---------------- layer 0 dense matmul: hwA = x @ W0  (128 -> 16) ----------
__global__ void k_mm0(const float* __restrict__ x, const float* __restrict__ W0) {
    __shared__ float sW[DIN * HH];            // 8 KB
    __shared__ float sx[16 * 129];            // padded stride vs bank conflicts
    int t = threadIdx.x;
    int nodeBase = blockIdx.x * 16;
    #pragma unroll
    for (int i = 0; i < 8; i++) sW[t + i * 256] = W0[t + i * 256];
    #pragma unroll
    for (int i = 0; i < 8; i++) {
        int idx = t + i * 256;                // 0..2047
        int nl = idx >> 7, k = idx & 127;
        sx[nl * 129 + k] = x[(nodeBase + nl) * DIN + k];
    }
    __syncthreads();
    int nl = t >> 4, f = t & 15;
    float acc = 0.f;
    #pragma unroll 16
    for (int k = 0; k < DIN; k++)
        acc = fmaf(sx[nl * 129 + k], sW[k * HH + f], acc);
    g_hwA[(nodeBase + nl) * HH + f] = acc;
}

// ---- shared edge-loop body: aggregate neighbor messages for (node g, feat f)
__device__ __forceinline__ float edge_agg(const float* __restrict__ hw,
                                          int s, int end, int f, float acc) {
    int e = s;
    // align to even index so int4 loads (2 edges / 16B) are aligned
    if ((e & 1) && e < end) {
        int2 ee = g_edge[e];
        acc = fmaf(__int_as_float(ee.y), __ldg(&hw[ee.x * HH + f]), acc);
        ++e;
    }
    const int4* ep = (const int4*)(g_edge + e);
    for (; e + 4 <= end; e += 4, ep += 2) {
        int4 p0 = ep[0];                     // edges e, e+1
        int4 p1 = ep[1];                     // edges e+2, e+3
        float a0 = __ldg(&hw[p0.x * HH + f]);
        float a1 = __ldg(&hw[p0.z * HH + f]);
        float a2 = __ldg(&hw[p1.x * HH + f]);
        float a3 = __ldg(&hw[p1.z * HH + f]);
        acc = fmaf(__int_as_float(p0.y), a0, acc);
        acc = fmaf(__int_as_float(p0.w), a1, acc);
        acc = fmaf(__int_as_float(p1.y), a2, acc);
        acc = fmaf(__int_as_float(p1.w), a3, acc);
    }
    for (; e < end; ++e) {
        int2 ee = g_edge[e];
        acc = fmaf(__int_as_float(ee.y), __ldg(&hw[ee.x * HH + f]), acc);
    }
    return acc;
}

// ---------------- fused aggregate + relu + next-layer 16xF matmul ----------
// 16 lanes per node (feature-parallel). Gather hw[src] rows (64B coalesced),
// then the next layer's matmul via warp shuffles.
__global__ void k_agg_fused(int pp, const float* __restrict__ bias,
                            const float* __restrict__ Wn, int fnext) {
    const float* __restrict__ hw  = pp ? g_hwB : g_hwA;
    float* __restrict__       out = pp ? g_hwA : g_hwB;
    __shared__ float sWn[HH * HH];
    __shared__ float sb[HH];
    int t = threadIdx.x;
    if (t < HH * fnext) sWn[t] = Wn[t];
    if (t < HH)         sb[t] = bias[t];
    __syncthreads();

    int g = blockIdx.x * 16 + (t >> 4);       // node id (grid covers NN exactly)
    int f = t & 15;
    int s = g_start[g];
    int end = s + g_cur[g];
    float acc = g_selfw[g] * hw[g * HH + f];
    acc = edge_agg(hw, s, end, f, acc);

    float h = fmaxf(acc + sb[f], 0.f);        // this conv's output feature f

    // next layer's matmul: o_f = sum_k h_k * Wn[k, f]
    float o = 0.f;
    int fc = (f < fnext) ? f : 0;
    #pragma unroll
    for (int k = 0; k < HH; k++) {
        float hk = __shfl_sync(0xffffffffu, h, k, 16);
        o = fmaf(hk, sWn[k * fnext + fc], o);
    }
    out[g * HH + f] = (f < fnext) ? o : 0.f;
}

// ---------------- final aggregate (12 features) -> output ------------------
__global__ void k_agg_final(int pp, const float* __restrict__ bias,
                            float* __restrict__ outp) {
    const float* __restrict__ hw = pp ? g_hwB : g_hwA;
    int t = threadIdx.x;
    int g = blockIdx.x * 16 + (t >> 4);
    int f = t & 15;
    int s = g_start[g];
    int end = s + g_cur[g];
    float acc = g_selfw[g] * hw[g * HH + f];
    acc = edge_agg(hw, s, end, f, acc);
    if (f < DOUT) outp[g * DOUT + f] = fmaxf(acc + bias[f], 0.f);
}

// ---------------- launch ----------------------------------------------------
extern "C" void kernel_launch(void* const* d_in, const int* in_sizes, int n_in,
                              void* d_out, int out_size) {
    const float* x     = (const float*)d_in[0];
    const int*   ei    = (const int*)d_in[1];
    const float* ew    = (const float*)d_in[2];
    const float* W0    = (const float*)d_in[3];
    const float* b0    = (const float*)d_in[4];
    const float* Wmid  = (const float*)d_in[5];
    const float* bmid  = (const float*)d_in[6];
    const float* Wlast = (const float*)d_in[7];
    const float* blast = (const float*)d_in[8];
    float*       out   = (float*)d_out;

    const int NB_N = (NN + 255) / 256;
    const int NB_E = (EE + 255) / 256;
    const int NB_G = NN / 16;                 // 6250, exact

    k_detect<<<1, 256>>>(ei);
    k_init  <<<NB_N, 256>>>();
    k_pass1 <<<NB_E, 256>>>(ei, ew);
    k_node  <<<NB_N, 256>>>();
    k_scan1 <<<98, 256>>>();
    k_scan2 <<<1, 128>>>(98);
    k_scan3 <<<98, 256>>>();
    k_scatter<<<NB_E, 256>>>(ei, ew);

    k_mm0   <<<NB_G, 256>>>(x, W0);           // -> g_hwA

    // conv0: bias b0, fuse Wmid[0]
    k_agg_fused<<<NB_G, 256>>>(0, b0, Wmid, HH);
    // conv 1..10: bias bmid[j-1], fuse Wmid[j]
    for (int j = 1; j <= 10; j++)
        k_agg_fused<<<NB_G, 256>>>(j & 1, bmid + (j - 1) * HH, Wmid + j * HH * HH, HH);
    // conv11: bias bmid[10], fuse Wlast (16 -> 12)
    k_agg_fused<<<NB_G, 256>>>(11 & 1, bmid + 10 * HH, Wlast, DOUT);
    // conv12: bias blast, final output
    k_agg_final<<<NB_G, 256>>>(0, blast, out);
}